// round 11
// baseline (speedup 1.0000x reference)
#include <cuda_runtime.h>

#define N 512
#define KC 16          // k-chunk
#define NCHUNK (N / KC)
#define NTILE 16       // 512/32 tile grid
#define NBLK (NTILE * (NTILE + 1) / 2)   // 136 upper-triangle blocks (one wave)
#define PAD 36         // SMEM row stride in floats: 144B keeps LDS.128 16B-aligned
#define NT 128         // threads per block (4 warps)

// Scratch (no allocations allowed).
__device__ float d_sim[N * N];
__device__ float d_acc;
__device__ unsigned d_done;   // ticket, wraps mod NBLK each replay
__device__ unsigned d_bar;    // monotonic grid-barrier counter (never reset)

// sigmoid(diff/0.01): sigmoid(x) = 0.5 + 0.5*tanh(x/2); tanh.approx saturates
// exactly where the reference's clipped sigmoid is 0/1, so the clip is free.
__device__ __forceinline__ float sig100(float diff) {
    float t;
    asm("tanh.approx.f32 %0, %1;" : "=f"(t) : "f"(50.0f * diff));
    return fmaf(0.5f, t, 0.5f);
}

// Phase-overlaid shared memory.
struct GemmS {                    // 13.4 KB
    float As[2][KC][PAD];
    float Bs[2][KC][PAD];
    float Ct[32][33];
};
struct P2S {                      // 16 KB
    float srow[4][N];             // one sim row per warp
    int   jl[4][N];               // per-warp j list (jl[w][0] = i, then positives)
};

__global__ __launch_bounds__(NT) void fused_kernel(const float* __restrict__ P,
                                                   const int* __restrict__ labels,
                                                   float* __restrict__ out) {
    __shared__ __align__(16) char smem_buf[sizeof(P2S) > sizeof(GemmS) ? sizeof(P2S) : sizeof(GemmS)];
    __shared__ int   slab[N];     // labels cache (outside the union)
    __shared__ float wsum[4];

    const int b = blockIdx.x;
    const int tid = threadIdx.x;
    const int lane = tid & 31, w = tid >> 5;

    if (b == 0 && tid == 0) d_acc = 0.0f;   // pre-barrier: ordered vs all adds

    // Labels cache (independent of GEMM results; load up-front).
    for (int idx = tid; idx < N; idx += NT) slab[idx] = labels[idx];

    // ================= Phase 1: GEMM sim = P*P^T (upper-triangle tiles) ====
    {
        GemmS* g = reinterpret_cast<GemmS*>(smem_buf);
        int bi = 0, rem = b;
        #pragma unroll
        for (int r = 0; r < NTILE; r++) {
            int c = NTILE - r;
            if (rem >= c) { rem -= c; bi++; } else break;
        }
        const int bj = bi + rem;
        const int row0 = bi * 32, col0 = bj * 32;

        const int tx = tid & 15;          // col pair
        const int ty = tid >> 4;          // row quad
        const int lrow = tid >> 2;        // load row 0..31
        const int lk = (tid & 3) * 4;     // load k offset

        float acc[4][2];
        #pragma unroll
        for (int m = 0; m < 4; m++) { acc[m][0] = 0.f; acc[m][1] = 0.f; }

        float4 ra = *reinterpret_cast<const float4*>(&P[(row0 + lrow) * N + lk]);
        float4 rb = *reinterpret_cast<const float4*>(&P[(col0 + lrow) * N + lk]);
        g->As[0][lk + 0][lrow] = ra.x; g->As[0][lk + 1][lrow] = ra.y;
        g->As[0][lk + 2][lrow] = ra.z; g->As[0][lk + 3][lrow] = ra.w;
        g->Bs[0][lk + 0][lrow] = rb.x; g->Bs[0][lk + 1][lrow] = rb.y;
        g->Bs[0][lk + 2][lrow] = rb.z; g->Bs[0][lk + 3][lrow] = rb.w;
        __syncthreads();

        for (int c = 0; c < NCHUNK; c++) {
            const int cur = c & 1;
            if (c + 1 < NCHUNK) {
                const int k0 = (c + 1) * KC;
                ra = *reinterpret_cast<const float4*>(&P[(row0 + lrow) * N + k0 + lk]);
                rb = *reinterpret_cast<const float4*>(&P[(col0 + lrow) * N + k0 + lk]);
            }
            #pragma unroll
            for (int kk = 0; kk < KC; kk++) {
                const float4 a = *reinterpret_cast<const float4*>(&g->As[cur][kk][ty * 4]);
                const float2 bb = *reinterpret_cast<const float2*>(&g->Bs[cur][kk][tx * 2]);
                acc[0][0] = fmaf(a.x, bb.x, acc[0][0]); acc[0][1] = fmaf(a.x, bb.y, acc[0][1]);
                acc[1][0] = fmaf(a.y, bb.x, acc[1][0]); acc[1][1] = fmaf(a.y, bb.y, acc[1][1]);
                acc[2][0] = fmaf(a.z, bb.x, acc[2][0]); acc[2][1] = fmaf(a.z, bb.y, acc[2][1]);
                acc[3][0] = fmaf(a.w, bb.x, acc[3][0]); acc[3][1] = fmaf(a.w, bb.y, acc[3][1]);
            }
            if (c + 1 < NCHUNK) {
                const int nxt = cur ^ 1;
                g->As[nxt][lk + 0][lrow] = ra.x; g->As[nxt][lk + 1][lrow] = ra.y;
                g->As[nxt][lk + 2][lrow] = ra.z; g->As[nxt][lk + 3][lrow] = ra.w;
                g->Bs[nxt][lk + 0][lrow] = rb.x; g->Bs[nxt][lk + 1][lrow] = rb.y;
                g->Bs[nxt][lk + 2][lrow] = rb.z; g->Bs[nxt][lk + 3][lrow] = rb.w;
            }
            __syncthreads();
        }

        #pragma unroll
        for (int m = 0; m < 4; m++) {
            float2 v = make_float2(acc[m][0], acc[m][1]);
            *reinterpret_cast<float2*>(&d_sim[(row0 + ty * 4 + m) * N + col0 + tx * 2]) = v;
        }
        if (bi != bj) {
            #pragma unroll
            for (int m = 0; m < 4; m++) {
                g->Ct[tx * 2 + 0][ty * 4 + m] = acc[m][0];
                g->Ct[tx * 2 + 1][ty * 4 + m] = acc[m][1];
            }
            __syncthreads();
            #pragma unroll
            for (int idx = tid; idx < 1024; idx += NT) {
                const int r2 = idx >> 5, c2 = idx & 31;
                d_sim[(col0 + r2) * N + row0 + c2] = g->Ct[r2][c2];
            }
        }
    }

    // ================= Grid barrier (136 blocks <= 148 SMs: one wave) ======
    __threadfence();
    __syncthreads();
    if (tid == 0) {
        const unsigned old = atomicAdd(&d_bar, 1u);
        const unsigned target = (old / NBLK + 1u) * NBLK;
        while (*(volatile unsigned*)&d_bar < target) { }
        __threadfence();
    }
    __syncthreads();    // also closes the GEMM->P2 smem union transition

    // ================= Phase 2: one WARP per anchor ========================
    P2S* p2 = reinterpret_cast<P2S*>(smem_buf);
    float pa = 0.0f;
    const int i = b * 4 + w;           // anchor (blocks 128..135 idle here)

    if (i < N) {
        // Load sim row i into this warp's SMEM slice (float4-coalesced).
        const float* rp = &d_sim[i * N];
        #pragma unroll
        for (int r = 0; r < 4; r++) {
            float4 v = *reinterpret_cast<const float4*>(&rp[r * 128 + lane * 4]);
            *reinterpret_cast<float4*>(&p2->srow[w][r * 128 + lane * 4]) = v;
        }
        __syncwarp();

        const int li = slab[i];
        float sreg[16], pf[16];
        int base = 1;
        if (lane == 0) p2->jl[w][0] = i;
        #pragma unroll
        for (int kt = 0; kt < 16; kt++) {
            const int k = lane + kt * 32;
            sreg[kt] = p2->srow[w][k];
            const bool p = (slab[k] == li) && (k != i);
            pf[kt] = p ? 1.0f : 0.0f;
            const unsigned bal = __ballot_sync(0xFFFFFFFFu, p);
            if (p) {
                const int rank = __popc(bal & ((1u << lane) - 1u));
                p2->jl[w][base + rank] = k;
            }
            base += __popc(bal);
        }
        __syncwarp();
        const int m1 = base;           // n_pos = m + 1

        float racc = 0.0f;
        for (int jj = 0; jj < m1; jj++) {
            const int j = p2->jl[w][jj];       // uniform LDS
            const float sj = p2->srow[w][j];   // uniform LDS (broadcast)
            float sa = 0.f, sp = 0.f;
            #pragma unroll
            for (int q = 0; q < 16; q++) {
                float gg = sig100(sreg[q] - sj);
                gg = (lane + q * 32 == j) ? 0.0f : gg;   // (1-eye)[j,k]
                sa += gg;
                sp = fmaf(gg, pf[q], sp);
            }
            #pragma unroll
            for (int o = 16; o; o >>= 1) {
                sa += __shfl_xor_sync(0xFFFFFFFFu, sa, o);
                sp += __shfl_xor_sync(0xFFFFFFFFu, sp, o);
            }
            racc += (jj == 0) ? 1.0f / (1.0f + sa)
                              : (1.0f + sp) / (1.0f + sa);
        }
        pa = (m1 > 1) ? racc / (float)m1 : 0.0f;    // where(n_pos>1)
    }

    if (lane == 0) wsum[w] = pa;
    __syncthreads();
    if (tid == 0) {
        atomicAdd(&d_acc, (wsum[0] + wsum[1]) + (wsum[2] + wsum[3]));
        __threadfence();
        const unsigned old = atomicInc(&d_done, NBLK - 1);   // wraps to 0
        if (old == NBLK - 1)
            out[0] = 1.0f - atomicAdd(&d_acc, 0.0f) / (float)N;
    }
}

extern "C" void kernel_launch(void* const* d_in, const int* in_sizes, int n_in,
                              void* d_out, int out_size) {
    const float* preds = (const float*)d_in[0];
    const int* labels = (const int*)d_in[1];
    float* out = (float*)d_out;

    fused_kernel<<<NBLK, NT>>>(preds, labels, out);
}

// round 12
// speedup vs baseline: 1.2551x; 1.2551x over previous
#include <cuda_runtime.h>

#define N 512
#define KC 16          // k-chunk
#define NCHUNK (N / KC)
#define NTILE 16       // 512/32 tile grid
#define NBLK (NTILE * (NTILE + 1) / 2)   // 136 upper-triangle blocks
#define PAD 36         // SMEM row stride in floats: 144B keeps LDS.128 16B-aligned
#define NB2 128        // smoothap blocks (4 warps each -> 512 warps = 512 anchors)

// Scratch (no allocations allowed).
__device__ float d_sim[N * N];
__device__ float d_acc;
__device__ unsigned d_done;   // ticket, wraps mod NB2 each replay

// sigmoid(diff/0.01): sigmoid(x) = 0.5 + 0.5*tanh(x/2); tanh.approx saturates
// exactly where the reference's clipped sigmoid is 0/1, so the clip is free.
__device__ __forceinline__ float sig100(float diff) {
    float t;
    asm("tanh.approx.f32 %0, %1;" : "=f"(t) : "f"(50.0f * diff));
    return fmaf(0.5f, t, 0.5f);
}

// --- Kernel 1: symmetric SGEMM sim = P*P^T ---------------------------------
// Upper-triangle 32x32 tiles, 136 blocks, 256 threads (8 warps: 2/SMSP for
// latency hiding). Each thread: 4 outputs (4 rows x 1 col). Per warp per k:
// broadcast LDS.128 (A-frag) + conflict-free LDS.32 (B) + 4 FFMA.
__global__ __launch_bounds__(256) void gemm_sym_kernel(const float* __restrict__ P) {
    if (blockIdx.x == 0 && threadIdx.x == 0) d_acc = 0.0f;

    // Map linear bid -> upper-triangle (bi, bj), bi <= bj.
    int bi = 0, rem = blockIdx.x;
    #pragma unroll
    for (int r = 0; r < NTILE; r++) {
        int c = NTILE - r;
        if (rem >= c) { rem -= c; bi++; } else break;
    }
    const int bj = bi + rem;
    const int row0 = bi * 32, col0 = bj * 32;

    __shared__ float As[2][KC][PAD];
    __shared__ float Bs[2][KC][PAD];
    __shared__ float Ct[32][33];

    const int tid = threadIdx.x;
    const int lane = tid & 31;        // output col
    const int w = tid >> 5;           // warp -> row quad (rows w*4..w*4+3)
    const int lrow = tid >> 3;        // load row 0..31
    const int lkp = (tid & 7) * 2;    // load k offset (even)

    float acc[4] = {0.f, 0.f, 0.f, 0.f};

    // Preload chunk 0 (float2 per thread per matrix).
    float2 ra = *reinterpret_cast<const float2*>(&P[(row0 + lrow) * N + lkp]);
    float2 rb = *reinterpret_cast<const float2*>(&P[(col0 + lrow) * N + lkp]);
    As[0][lkp + 0][lrow] = ra.x; As[0][lkp + 1][lrow] = ra.y;
    Bs[0][lkp + 0][lrow] = rb.x; Bs[0][lkp + 1][lrow] = rb.y;
    __syncthreads();

    for (int c = 0; c < NCHUNK; c++) {
        const int cur = c & 1;
        if (c + 1 < NCHUNK) {
            const int k0 = (c + 1) * KC;
            ra = *reinterpret_cast<const float2*>(&P[(row0 + lrow) * N + k0 + lkp]);
            rb = *reinterpret_cast<const float2*>(&P[(col0 + lrow) * N + k0 + lkp]);
        }
        #pragma unroll
        for (int kk = 0; kk < KC; kk++) {
            const float4 a = *reinterpret_cast<const float4*>(&As[cur][kk][w * 4]); // broadcast
            const float  b = Bs[cur][kk][lane];                                      // 32 banks
            acc[0] = fmaf(a.x, b, acc[0]);
            acc[1] = fmaf(a.y, b, acc[1]);
            acc[2] = fmaf(a.z, b, acc[2]);
            acc[3] = fmaf(a.w, b, acc[3]);
        }
        if (c + 1 < NCHUNK) {
            const int nxt = cur ^ 1;
            As[nxt][lkp + 0][lrow] = ra.x; As[nxt][lkp + 1][lrow] = ra.y;
            Bs[nxt][lkp + 0][lrow] = rb.x; Bs[nxt][lkp + 1][lrow] = rb.y;
        }
        __syncthreads();
    }

    // Write C tile (coalesced 32-float rows).
    #pragma unroll
    for (int m = 0; m < 4; m++)
        d_sim[(row0 + w * 4 + m) * N + col0 + lane] = acc[m];

    // Off-diagonal: also write the transpose via SMEM staging.
    if (bi != bj) {
        #pragma unroll
        for (int m = 0; m < 4; m++)
            Ct[lane][w * 4 + m] = acc[m];
        __syncthreads();
        #pragma unroll
        for (int idx = tid; idx < 1024; idx += 256) {
            const int r2 = idx >> 5, c2 = idx & 31;
            d_sim[(col0 + r2) * N + row0 + c2] = Ct[r2][c2];
        }
    }
}

// --- Kernel 2: SmoothAP, one WARP per anchor -------------------------------
// sim_pos_rk[i,j] == 0 unless j == i or labels[j] == labels[i]: only ~9 of
// 512 j's per anchor need the k-reduction. 128 blocks x 4 warps = 512 warps.
// Row lives in registers (sreg[16]); positive list built with ballot/popc.
__global__ __launch_bounds__(128) void smoothap_kernel(const int* __restrict__ labels,
                                                       float* __restrict__ out) {
    __shared__ float srow[4][N];   // per-warp sim row (random access for sj)
    __shared__ int   jl[4][N];     // per-warp j list (jl[w][0] = i, then positives)
    __shared__ int   slab[N];      // labels cache
    __shared__ float wsum[4];

    const int b = blockIdx.x;
    const int tid = threadIdx.x;
    const int lane = tid & 31, w = tid >> 5;
    const int i = b * 4 + w;       // anchor for this warp (all 512 covered)

    for (int idx = tid; idx < N; idx += 128) slab[idx] = labels[idx];
    __syncthreads();

    // Load sim row i (float4-coalesced) into SMEM + registers.
    const float* rp = &d_sim[i * N];
    #pragma unroll
    for (int r = 0; r < 4; r++) {
        float4 v = *reinterpret_cast<const float4*>(&rp[r * 128 + lane * 4]);
        *reinterpret_cast<float4*>(&srow[w][r * 128 + lane * 4]) = v;
    }
    __syncwarp();

    const int li = slab[i];
    float sreg[16], pf[16];
    int base = 1;
    if (lane == 0) jl[w][0] = i;
    #pragma unroll
    for (int kt = 0; kt < 16; kt++) {
        const int k = lane + kt * 32;
        sreg[kt] = srow[w][k];
        const bool p = (slab[k] == li) && (k != i);
        pf[kt] = p ? 1.0f : 0.0f;
        const unsigned bal = __ballot_sync(0xFFFFFFFFu, p);
        if (p) {
            const int rank = __popc(bal & ((1u << lane) - 1u));
            jl[w][base + rank] = k;
        }
        base += __popc(bal);
    }
    __syncwarp();
    const int m1 = base;           // n_pos = m + 1

    float racc = 0.0f;
    for (int jj = 0; jj < m1; jj++) {
        const int j = jl[w][jj];        // uniform LDS
        const float sj = srow[w][j];    // uniform LDS (broadcast)
        float sa = 0.f, sp = 0.f;
        #pragma unroll
        for (int q = 0; q < 16; q++) {
            float gg = sig100(sreg[q] - sj);
            gg = (lane + q * 32 == j) ? 0.0f : gg;   // (1-eye)[j,k]
            sa += gg;
            sp = fmaf(gg, pf[q], sp);
        }
        #pragma unroll
        for (int o = 16; o; o >>= 1) {
            sa += __shfl_xor_sync(0xFFFFFFFFu, sa, o);
            sp += __shfl_xor_sync(0xFFFFFFFFu, sp, o);
        }
        racc += (jj == 0) ? 1.0f / (1.0f + sa)
                          : (1.0f + sp) / (1.0f + sa);
    }
    const float pa = (m1 > 1) ? racc / (float)m1 : 0.0f;   // where(n_pos>1)

    if (lane == 0) wsum[w] = pa;
    __syncthreads();
    if (tid == 0) {
        atomicAdd(&d_acc, (wsum[0] + wsum[1]) + (wsum[2] + wsum[3]));
        __threadfence();
        const unsigned old = atomicInc(&d_done, NB2 - 1);   // wraps to 0
        if (old == NB2 - 1)
            out[0] = 1.0f - atomicAdd(&d_acc, 0.0f) / (float)N;
    }
}

extern "C" void kernel_launch(void* const* d_in, const int* in_sizes, int n_in,
                              void* d_out, int out_size) {
    const float* preds = (const float*)d_in[0];
    const int* labels = (const int*)d_in[1];
    float* out = (float*)d_out;

    gemm_sym_kernel<<<NBLK, 256>>>(preds);
    smoothap_kernel<<<NB2, 128>>>(labels, out);
}

// round 14
// speedup vs baseline: 1.3957x; 1.1121x over previous
#include <cuda_runtime.h>

#define N 512
#define KC 16
#define KHALF 256
#define NCH (KHALF / KC)                  // 16 chunks per k-half
#define NTILE 16
#define NTRI (NTILE * (NTILE + 1) / 2)    // 136 upper-triangle tiles
#define NGEMM (2 * NTRI)                  // 272 GEMM blocks (tile x k-half)
#define NBLK 512                          // grid size (one wave: 3.46 blk/SM)
#define PAD 36                            // SMEM row stride: 144B, 16B-aligned
#define NT 128                            // threads per block

// Scratch (no allocations allowed).
__device__ float d_simA[N * N];           // k in [0,256) partial
__device__ float d_simB[N * N];           // k in [256,512) partial
__device__ float d_acc;
__device__ unsigned d_done;               // ticket, wraps mod NBLK per replay
__device__ unsigned d_bar;                // monotonic barrier counter

// sigmoid(diff/0.01): 0.5 + 0.5*tanh(50*diff); tanh.approx saturates exactly
// where the reference's clipped sigmoid is 0/1, so the clip is free.
__device__ __forceinline__ float sig100(float diff) {
    float t;
    asm("tanh.approx.f32 %0, %1;" : "=f"(t) : "f"(50.0f * diff));
    return fmaf(0.5f, t, 0.5f);
}

struct GemmS {                            // 13.4 KB
    float As[2][KC][PAD];
    float Bs[2][KC][PAD];
    float Ct[32][33];
};
struct P2S {                              // 8 KB
    float s[N];                           // combined sim row
    float pf[N];                          // positive mask
    int   jl[N];                          // j list: jl[0]=i, then positives
    int   slab[N];                        // labels cache
};

__global__ __launch_bounds__(NT, 4) void fused_kernel(const float* __restrict__ P,
                                                      const int* __restrict__ labels,
                                                      float* __restrict__ out) {
    __shared__ __align__(16) char sm[sizeof(GemmS)];   // GemmS > P2S
    __shared__ int cnt;
    __shared__ float ssum;

    const int b = blockIdx.x;
    const int tid = threadIdx.x;
    const int lane = tid & 31, w = tid >> 5;

    if (b == 0 && tid == 0) d_acc = 0.0f;   // pre-barrier: ordered vs adds

    // ============ Phase 1: split-K symmetric SGEMM (blocks 0..271) =========
    if (b < NGEMM) {
        GemmS* g = reinterpret_cast<GemmS*>(sm);
        const int t = b >> 1, kh = b & 1, kbase = kh * KHALF;
        int bi = 0, rem = t;
        #pragma unroll
        for (int r = 0; r < NTILE; r++) {
            int c = NTILE - r;
            if (rem >= c) { rem -= c; bi++; } else break;
        }
        const int bj = bi + rem;
        const int row0 = bi * 32, col0 = bj * 32;
        float* dst = kh ? d_simB : d_simA;

        const int tx = tid & 15;          // col pair
        const int ty = tid >> 4;          // row quad
        const int lrow = tid >> 2;        // load row 0..31
        const int lk = (tid & 3) * 4;     // load k offset

        float acc[4][2];
        #pragma unroll
        for (int m = 0; m < 4; m++) { acc[m][0] = 0.f; acc[m][1] = 0.f; }

        float4 ra = *reinterpret_cast<const float4*>(&P[(row0 + lrow) * N + kbase + lk]);
        float4 rb = *reinterpret_cast<const float4*>(&P[(col0 + lrow) * N + kbase + lk]);
        g->As[0][lk + 0][lrow] = ra.x; g->As[0][lk + 1][lrow] = ra.y;
        g->As[0][lk + 2][lrow] = ra.z; g->As[0][lk + 3][lrow] = ra.w;
        g->Bs[0][lk + 0][lrow] = rb.x; g->Bs[0][lk + 1][lrow] = rb.y;
        g->Bs[0][lk + 2][lrow] = rb.z; g->Bs[0][lk + 3][lrow] = rb.w;
        __syncthreads();

        for (int c = 0; c < NCH; c++) {
            const int cur = c & 1;
            if (c + 1 < NCH) {
                const int k0 = kbase + (c + 1) * KC;
                ra = *reinterpret_cast<const float4*>(&P[(row0 + lrow) * N + k0 + lk]);
                rb = *reinterpret_cast<const float4*>(&P[(col0 + lrow) * N + k0 + lk]);
            }
            #pragma unroll
            for (int kk = 0; kk < KC; kk++) {
                const float4 a = *reinterpret_cast<const float4*>(&g->As[cur][kk][ty * 4]);
                const float2 bb = *reinterpret_cast<const float2*>(&g->Bs[cur][kk][tx * 2]);
                acc[0][0] = fmaf(a.x, bb.x, acc[0][0]); acc[0][1] = fmaf(a.x, bb.y, acc[0][1]);
                acc[1][0] = fmaf(a.y, bb.x, acc[1][0]); acc[1][1] = fmaf(a.y, bb.y, acc[1][1]);
                acc[2][0] = fmaf(a.z, bb.x, acc[2][0]); acc[2][1] = fmaf(a.z, bb.y, acc[2][1]);
                acc[3][0] = fmaf(a.w, bb.x, acc[3][0]); acc[3][1] = fmaf(a.w, bb.y, acc[3][1]);
            }
            if (c + 1 < NCH) {
                const int nxt = cur ^ 1;
                g->As[nxt][lk + 0][lrow] = ra.x; g->As[nxt][lk + 1][lrow] = ra.y;
                g->As[nxt][lk + 2][lrow] = ra.z; g->As[nxt][lk + 3][lrow] = ra.w;
                g->Bs[nxt][lk + 0][lrow] = rb.x; g->Bs[nxt][lk + 1][lrow] = rb.y;
                g->Bs[nxt][lk + 2][lrow] = rb.z; g->Bs[nxt][lk + 3][lrow] = rb.w;
            }
            __syncthreads();
        }

        #pragma unroll
        for (int m = 0; m < 4; m++) {
            float2 v = make_float2(acc[m][0], acc[m][1]);
            *reinterpret_cast<float2*>(&dst[(row0 + ty * 4 + m) * N + col0 + tx * 2]) = v;
        }
        if (bi != bj) {                   // mirror tile via SMEM transpose
            #pragma unroll
            for (int m = 0; m < 4; m++) {
                g->Ct[tx * 2 + 0][ty * 4 + m] = acc[m][0];
                g->Ct[tx * 2 + 1][ty * 4 + m] = acc[m][1];
            }
            __syncthreads();
            #pragma unroll
            for (int idx = tid; idx < 1024; idx += NT) {
                const int r2 = idx >> 5, c2 = idx & 31;
                dst[(col0 + r2) * N + row0 + c2] = g->Ct[r2][c2];
            }
        }
    }

    // ============ Grid barrier (all 512 blocks resident: one wave) =========
    __threadfence();
    __syncthreads();
    if (tid == 0) {
        const unsigned old = atomicAdd(&d_bar, 1u);
        const unsigned target = (old / NBLK + 1u) * NBLK;
        while (*(volatile unsigned*)&d_bar < target) { }
        __threadfence();
    }
    __syncthreads();    // also closes the GEMM->P2 smem union transition

    // ============ Phase 2: one BLOCK per anchor i = b ======================
    P2S* p = reinterpret_cast<P2S*>(sm);
    const int i = b;

    for (int idx = tid; idx < N; idx += NT) p->slab[idx] = labels[idx];
    {   // combined row: s[k] = A[i,k] + B[i,k]
        const float4 a4 = *reinterpret_cast<const float4*>(&d_simA[i * N + tid * 4]);
        const float4 b4 = *reinterpret_cast<const float4*>(&d_simB[i * N + tid * 4]);
        float4 v;
        v.x = a4.x + b4.x; v.y = a4.y + b4.y; v.z = a4.z + b4.z; v.w = a4.w + b4.w;
        *reinterpret_cast<float4*>(&p->s[tid * 4]) = v;
    }
    if (tid == 0) { cnt = 1; ssum = 0.0f; p->jl[0] = i; }
    __syncthreads();

    const int li = p->slab[i];
    for (int k = tid; k < N; k += NT) {
        const bool pp = (p->slab[k] == li) && (k != i);
        p->pf[k] = pp ? 1.0f : 0.0f;
        if (pp) p->jl[atomicAdd(&cnt, 1)] = k;
    }
    __syncthreads();
    const int m1 = cnt;                  // n_pos = m + 1

    for (int jj = w; jj < m1; jj += NT / 32) {
        const int j = p->jl[jj];
        const float sj = p->s[j];
        float sa = 0.f, sp = 0.f;
        #pragma unroll
        for (int q = 0; q < 16; q++) {
            const int k = lane + q * 32;
            float gg = sig100(p->s[k] - sj);
            gg = (k == j) ? 0.0f : gg;   // (1-eye)[j,k]
            sa += gg;
            sp = fmaf(gg, p->pf[k], sp);
        }
        #pragma unroll
        for (int o = 16; o; o >>= 1) {
            sa += __shfl_xor_sync(0xFFFFFFFFu, sa, o);
            sp += __shfl_xor_sync(0xFFFFFFFFu, sp, o);
        }
        if (lane == 0)
            atomicAdd(&ssum, (jj == 0) ? 1.0f / (1.0f + sa)
                                       : (1.0f + sp) / (1.0f + sa));
    }
    __syncthreads();

    if (tid == 0) {
        const float pa = (m1 > 1) ? ssum / (float)m1 : 0.0f;   // where(n_pos>1)
        atomicAdd(&d_acc, pa);
        __threadfence();
        const unsigned old = atomicInc(&d_done, NBLK - 1);     // wraps to 0
        if (old == NBLK - 1)
            out[0] = 1.0f - atomicAdd(&d_acc, 0.0f) / (float)N;
    }
}

extern "C" void kernel_launch(void* const* d_in, const int* in_sizes, int n_in,
                              void* d_out, int out_size) {
    const float* preds = (const float*)d_in[0];
    const int* labels = (const int*)d_in[1];
    float* out = (float*)d_out;

    fused_kernel<<<NBLK, NT>>>(preds, labels, out);
}

// round 15
// speedup vs baseline: 1.8636x; 1.3352x over previous
#include <cuda_runtime.h>

#define N 512
#define KC 16
#define KQ 128                            // k-quarter per GEMM block
#define NCH (KQ / KC)                     // 8 chunks
#define NTILE 16
#define NTRI (NTILE * (NTILE + 1) / 2)    // 136 upper-triangle tiles
#define NGEMM (4 * NTRI)                  // 544 blocks (tile x k-quarter)
#define PAD 36                            // SMEM row stride: 144B, 16B-aligned
#define NB2 512                           // smoothap blocks
#define NT2 256                           // smoothap threads

// Scratch (no allocations allowed).
__device__ float d_simP[4][N * N];        // split-K partials
__device__ float d_acc;
__device__ unsigned d_done;               // ticket, wraps mod NB2 per replay

// sigmoid(diff/0.01): 0.5 + 0.5*tanh(50*diff); tanh.approx saturates exactly
// where the reference's clipped sigmoid is 0/1, so the clip is free.
__device__ __forceinline__ float sig100(float diff) {
    float t;
    asm("tanh.approx.f32 %0, %1;" : "=f"(t) : "f"(50.0f * diff));
    return fmaf(0.5f, t, 0.5f);
}

// --- Kernel 1: split-K(x4) symmetric SGEMM sim = P*P^T ---------------------
// 136 upper-triangle 32x32 tiles x 4 k-quarters = 544 blocks, 128 threads,
// 8 outputs/thread (4 rows x 2 cols). ~3.7 blocks/SM -> latency hidden.
__global__ __launch_bounds__(128) void gemm_sym_kernel(const float* __restrict__ P) {
    if (blockIdx.x == 0 && threadIdx.x == 0) d_acc = 0.0f;

    const int t = blockIdx.x >> 2, kq = blockIdx.x & 3, kbase = kq * KQ;
    int bi = 0, rem = t;
    #pragma unroll
    for (int r = 0; r < NTILE; r++) {
        int c = NTILE - r;
        if (rem >= c) { rem -= c; bi++; } else break;
    }
    const int bj = bi + rem;
    const int row0 = bi * 32, col0 = bj * 32;
    float* __restrict__ dst = d_simP[kq];

    __shared__ float As[2][KC][PAD];
    __shared__ float Bs[2][KC][PAD];
    __shared__ float Ct[32][33];

    const int tid = threadIdx.x;
    const int tx = tid & 15;          // col pair
    const int ty = tid >> 4;          // row quad
    const int lrow = tid >> 2;        // load row 0..31
    const int lk = (tid & 3) * 4;     // load k offset

    float acc[4][2];
    #pragma unroll
    for (int m = 0; m < 4; m++) { acc[m][0] = 0.f; acc[m][1] = 0.f; }

    float4 ra = *reinterpret_cast<const float4*>(&P[(row0 + lrow) * N + kbase + lk]);
    float4 rb = *reinterpret_cast<const float4*>(&P[(col0 + lrow) * N + kbase + lk]);
    As[0][lk + 0][lrow] = ra.x; As[0][lk + 1][lrow] = ra.y;
    As[0][lk + 2][lrow] = ra.z; As[0][lk + 3][lrow] = ra.w;
    Bs[0][lk + 0][lrow] = rb.x; Bs[0][lk + 1][lrow] = rb.y;
    Bs[0][lk + 2][lrow] = rb.z; Bs[0][lk + 3][lrow] = rb.w;
    __syncthreads();

    for (int c = 0; c < NCH; c++) {
        const int cur = c & 1;
        if (c + 1 < NCH) {
            const int k0 = kbase + (c + 1) * KC;
            ra = *reinterpret_cast<const float4*>(&P[(row0 + lrow) * N + k0 + lk]);
            rb = *reinterpret_cast<const float4*>(&P[(col0 + lrow) * N + k0 + lk]);
        }
        #pragma unroll
        for (int kk = 0; kk < KC; kk++) {
            const float4 a = *reinterpret_cast<const float4*>(&As[cur][kk][ty * 4]);
            const float2 bb = *reinterpret_cast<const float2*>(&Bs[cur][kk][tx * 2]);
            acc[0][0] = fmaf(a.x, bb.x, acc[0][0]); acc[0][1] = fmaf(a.x, bb.y, acc[0][1]);
            acc[1][0] = fmaf(a.y, bb.x, acc[1][0]); acc[1][1] = fmaf(a.y, bb.y, acc[1][1]);
            acc[2][0] = fmaf(a.z, bb.x, acc[2][0]); acc[2][1] = fmaf(a.z, bb.y, acc[2][1]);
            acc[3][0] = fmaf(a.w, bb.x, acc[3][0]); acc[3][1] = fmaf(a.w, bb.y, acc[3][1]);
        }
        if (c + 1 < NCH) {
            const int nxt = cur ^ 1;
            As[nxt][lk + 0][lrow] = ra.x; As[nxt][lk + 1][lrow] = ra.y;
            As[nxt][lk + 2][lrow] = ra.z; As[nxt][lk + 3][lrow] = ra.w;
            Bs[nxt][lk + 0][lrow] = rb.x; Bs[nxt][lk + 1][lrow] = rb.y;
            Bs[nxt][lk + 2][lrow] = rb.z; Bs[nxt][lk + 3][lrow] = rb.w;
        }
        __syncthreads();
    }

    #pragma unroll
    for (int m = 0; m < 4; m++) {
        float2 v = make_float2(acc[m][0], acc[m][1]);
        *reinterpret_cast<float2*>(&dst[(row0 + ty * 4 + m) * N + col0 + tx * 2]) = v;
    }
    if (bi != bj) {                   // mirror tile via SMEM transpose
        #pragma unroll
        for (int m = 0; m < 4; m++) {
            Ct[tx * 2 + 0][ty * 4 + m] = acc[m][0];
            Ct[tx * 2 + 1][ty * 4 + m] = acc[m][1];
        }
        __syncthreads();
        #pragma unroll
        for (int idx = tid; idx < 1024; idx += 128) {
            const int r2 = idx >> 5, c2 = idx & 31;
            dst[(col0 + r2) * N + row0 + c2] = Ct[r2][c2];
        }
    }
}

// --- Kernel 2: SmoothAP body, positives-only (proven R4 shape) -------------
// One block per anchor (512 x 256 threads); row assembled from 4 partials.
// Only ~9 of 512 j's per anchor need the k-reduction; jobs striped on warps.
__global__ __launch_bounds__(NT2) void smoothap_kernel(const int* __restrict__ labels,
                                                       float* __restrict__ out) {
    const int i = blockIdx.x;
    const int t = threadIdx.x;

    __shared__ float s[N];       // combined sim row
    __shared__ float pflag[N];   // positive mask
    __shared__ int   jlist[N];   // jlist[0] = i, then positive indices
    __shared__ int   cnt;
    __shared__ float ssum;

    if (t == 0) { cnt = 1; ssum = 0.0f; jlist[0] = i; }
    __syncthreads();

    {   // s[k] = sum of 4 split-K partials (float2-coalesced)
        const int k2 = t * 2;
        float2 v = make_float2(0.f, 0.f);
        #pragma unroll
        for (int q = 0; q < 4; q++) {
            const float2 u = *reinterpret_cast<const float2*>(&d_simP[q][i * N + k2]);
            v.x += u.x; v.y += u.y;
        }
        *reinterpret_cast<float2*>(&s[k2]) = v;
    }

    const int li = labels[i];
    #pragma unroll
    for (int k = t; k < N; k += NT2) {
        const bool p = (labels[k] == li) && (k != i);
        pflag[k] = p ? 1.0f : 0.0f;
        if (p) jlist[atomicAdd(&cnt, 1)] = k;
    }
    __syncthreads();

    const int m1 = cnt;                 // n_pos = m + 1
    const int lane = t & 31, w = t >> 5;

    for (int jj = w; jj < m1; jj += NT2 / 32) {
        const int j = jlist[jj];
        const float sj = s[j];
        float sa = 0.0f, sp = 0.0f;
        #pragma unroll
        for (int it = 0; it < N / 32; it++) {
            const int k = lane + it * 32;
            float g = sig100(s[k] - sj);
            g = (k == j) ? 0.0f : g;    // (1-eye)[j,k] mask
            sa += g;
            sp = fmaf(g, pflag[k], sp);
        }
        #pragma unroll
        for (int o = 16; o; o >>= 1) {
            sa += __shfl_xor_sync(0xFFFFFFFFu, sa, o);
            sp += __shfl_xor_sync(0xFFFFFFFFu, sp, o);
        }
        if (lane == 0) {
            const float ratio = (jj == 0) ? 1.0f / (1.0f + sa)
                                          : (1.0f + sp) / (1.0f + sa);
            atomicAdd(&ssum, ratio);
        }
    }
    __syncthreads();

    if (t == 0) {
        const float pa = (m1 > 1) ? ssum / (float)m1 : 0.0f;  // where(n_pos>1)
        atomicAdd(&d_acc, pa);
        __threadfence();
        const unsigned old = atomicInc(&d_done, NB2 - 1);     // wraps to 0
        if (old == NB2 - 1)
            out[0] = 1.0f - atomicAdd(&d_acc, 0.0f) / (float)N;
    }
}

extern "C" void kernel_launch(void* const* d_in, const int* in_sizes, int n_in,
                              void* d_out, int out_size) {
    const float* preds = (const float*)d_in[0];
    const int* labels = (const int*)d_in[1];
    float* out = (float*)d_out;

    gemm_sym_kernel<<<NGEMM, 128>>>(preds);
    smoothap_kernel<<<NB2, NT2>>>(labels, out);
}